// round 10
// baseline (speedup 1.0000x reference)
#include <cuda_runtime.h>
#include <cuda_fp16.h>
#include <cstdint>
#include <cstddef>

// ---------------------------------------------------------------------------
// Problem constants
// ---------------------------------------------------------------------------
constexpr int Bb = 64;
constexpr int Ss = 2048;
constexpr int Hh = 1024;
constexpr int Kk = 2048;          // 2H reduction dim
constexpr int BS = Bb * Ss;       // 131072 rows
constexpr int MT = 128;           // CTA M tile
constexpr int NT = 128;           // CTA N tile
constexpr int NTILES = Hh / NT;   // 8
constexpr int KCH = 64;           // K chunk (halves)
constexpr int NCH = Kk / KCH;     // 32 chunks
constexpr int STAGES = 3;

// Padded smem strides (halves) — rows ≡ 16 mod 128 bytes: conflict-free ldmatrix
constexpr int ASTR = KCH + 8;     // 72 halves = 144B rows
constexpr int BSTR = NT + 8;      // 136 halves = 272B rows
constexpr int ABYTES = MT * ASTR * 2;    // 18432 per stage
constexpr int BBYTES = KCH * BSTR * 2;   // 17408 per stage

// Dynamic smem layout (bytes)
constexpr int OFF_A = 0;
constexpr int OFF_B = OFF_A + STAGES * ABYTES;      // 55296
constexpr int OFF_T = OFF_B + STAGES * BBYTES;      // 107520
constexpr int OFF_V = OFF_T + NT * 4;               // 108032
constexpr int OFF_PE = OFF_V + NT * 4;              // 108544
constexpr int SM_TOTAL = OFF_PE + 4 * MT * 4;       // 110592 (108 KB -> 2 CTAs/SM)

// Scratch (__device__ globals: allocation-free contract)
__device__ float  g_decf[Bb * Hh];
__device__ float  g_pe[NTILES * BS];
__device__ __half g_Wsh[(size_t)Kk * Hh];          // Ws in fp16, [K][H]
__device__ __half g_Eh[(size_t)BS * Kk];           // E in fp16,  [BS][2H]

__device__ __forceinline__ float fast_tanh(float x) {
    float y; asm("tanh.approx.f32 %0, %1;" : "=f"(y) : "f"(x)); return y;
}

// ---------------------------------------------------------------------------
// Kernel 0: dec_f = dh @ Wh
// ---------------------------------------------------------------------------
__global__ void decf_kernel(const float* __restrict__ dh,
                            const float* __restrict__ Wh) {
    __shared__ float dh_s[Hh];
    const int b = blockIdx.y;
    const int k = blockIdx.x * 128 + threadIdx.x;
    for (int h = threadIdx.x; h < Hh; h += 128) dh_s[h] = dh[b * Hh + h];
    __syncthreads();
    float acc = 0.f;
#pragma unroll 8
    for (int h = 0; h < Hh; ++h) acc += dh_s[h] * Wh[h * Hh + k];
    g_decf[b * Hh + k] = acc;
}

// ---------------------------------------------------------------------------
// Kernel 0b/0c: fp32 -> fp16 elementwise converts (memory-bound)
// ---------------------------------------------------------------------------
__global__ void cvt_ws_kernel(const float* __restrict__ Ws) {
    const size_t i4 = (size_t)blockIdx.x * 256 + threadIdx.x;
    float4 f = reinterpret_cast<const float4*>(Ws)[i4];
    __half2 h0 = __floats2half2_rn(f.x, f.y);
    __half2 h1 = __floats2half2_rn(f.z, f.w);
    uint2 u; u.x = *(uint32_t*)&h0; u.y = *(uint32_t*)&h1;
    reinterpret_cast<uint2*>(g_Wsh)[i4] = u;
}
__global__ void cvt_e_kernel(const float* __restrict__ E) {
    const size_t i4 = (size_t)blockIdx.x * 256 + threadIdx.x;
    float4 f = reinterpret_cast<const float4*>(E)[i4];
    __half2 h0 = __floats2half2_rn(f.x, f.y);
    __half2 h1 = __floats2half2_rn(f.z, f.w);
    uint2 u; u.x = *(uint32_t*)&h0; u.y = *(uint32_t*)&h1;
    reinterpret_cast<uint2*>(g_Eh)[i4] = u;
}

// ---------------------------------------------------------------------------
// Kernel 1: fused energy GEMM (mma.sync, 3-stage cp.async, 2 CTAs/SM).
//   acc[128,128] = Eh_tile @ Wsh_tile (K=2048, fp32 acc), warp tile 64x32.
//   partial_energy[row] = sum_n tanh(acc + dec_f) * v   -> g_pe[ntile]
// ---------------------------------------------------------------------------
__global__ __launch_bounds__(256, 2)
void energy_kernel(const float* __restrict__ v) {
    extern __shared__ char sm[];
    const uint32_t sb = (uint32_t)__cvta_generic_to_shared(sm);
    const int tid = threadIdx.x, wid = tid >> 5, lane = tid & 31;
    const int wm = wid >> 2, wn = wid & 3;       // warp grid 2x4, tile 64x32
    const int g = lane >> 2, tq = lane & 3;
    const int nt = blockIdx.x;                   // 0..7 fastest: L2 reuse of A
    const int m0 = blockIdx.y * MT;
    const int n0 = nt * NT;
    const int batch = m0 >> 11;                  // m0 / Ss

    float* t_s = (float*)(sm + OFF_T);
    float* v_s = (float*)(sm + OFF_V);
    if (tid < NT) {
        t_s[tid] = g_decf[batch * Hh + n0 + tid];
        v_s[tid] = v[n0 + tid];
    }

    float acc[4][4][4];                          // 64 regs
#pragma unroll
    for (int i = 0; i < 4; ++i)
#pragma unroll
        for (int j = 0; j < 4; ++j)
#pragma unroll
            for (int q = 0; q < 4; ++q) acc[i][j][q] = 0.f;

    auto load_stage = [&](int st, int kc) {
        const uint32_t ab = sb + OFF_A + st * ABYTES;
#pragma unroll
        for (int i = 0; i < 4; ++i) {            // A: 1024 x 16B chunks
            const int c = tid + i * 256;
            const int row = c >> 3, o = c & 7;
            const uint32_t dst = ab + row * 144 + o * 16;
            const __half* src = &g_Eh[(size_t)(m0 + row) * Kk + kc + o * 8];
            asm volatile("cp.async.cg.shared.global [%0], [%1], 16;"
                         :: "r"(dst), "l"(src) : "memory");
        }
        const uint32_t bb = sb + OFF_B + st * BBYTES;
#pragma unroll
        for (int i = 0; i < 4; ++i) {            // B: 1024 x 16B chunks
            const int c = tid + i * 256;
            const int kr = c >> 4, o = c & 15;
            const uint32_t dst = bb + kr * 272 + o * 16;
            const __half* src = &g_Wsh[(size_t)(kc + kr) * Hh + n0 + o * 8];
            asm volatile("cp.async.cg.shared.global [%0], [%1], 16;"
                         :: "r"(dst), "l"(src) : "memory");
        }
        asm volatile("cp.async.commit_group;" ::: "memory");
    };

    load_stage(0, 0);
    load_stage(1, KCH);

    for (int c = 0; c < NCH; ++c) {
        const int st = c % STAGES;
        asm volatile("cp.async.wait_group 1;" ::: "memory");
        __syncthreads();
        if (c + 2 < NCH) load_stage((c + 2) % STAGES, (c + 2) * KCH);

        const uint32_t ab = sb + OFF_A + st * ABYTES;
        const uint32_t bb = sb + OFF_B + st * BBYTES;
#pragma unroll
        for (int ks = 0; ks < 4; ++ks) {
            const int k0 = ks * 16;
            uint32_t a[4][4], b[4][2];
#pragma unroll
            for (int mi = 0; mi < 4; ++mi) {
                const uint32_t addr = ab + (wm * 64 + mi * 16 + (lane & 15)) * 144
                                    + (k0 + (lane >> 4) * 8) * 2;
                asm volatile(
                    "ldmatrix.sync.aligned.m8n8.x4.shared.b16 {%0,%1,%2,%3}, [%4];"
                    : "=r"(a[mi][0]), "=r"(a[mi][1]), "=r"(a[mi][2]), "=r"(a[mi][3])
                    : "r"(addr));
            }
#pragma unroll
            for (int np = 0; np < 2; ++np) {     // 2 n-octets per x4.trans
                const uint32_t addr = bb + (k0 + (lane & 15)) * 272
                                    + (wn * 32 + np * 16 + (lane >> 4) * 8) * 2;
                asm volatile(
                    "ldmatrix.sync.aligned.m8n8.x4.trans.shared.b16 {%0,%1,%2,%3}, [%4];"
                    : "=r"(b[2 * np][0]), "=r"(b[2 * np][1]),
                      "=r"(b[2 * np + 1][0]), "=r"(b[2 * np + 1][1])
                    : "r"(addr));
            }
#pragma unroll
            for (int mi = 0; mi < 4; ++mi)
#pragma unroll
                for (int ni = 0; ni < 4; ++ni) {
                    asm volatile(
                        "mma.sync.aligned.m16n8k16.row.col.f32.f16.f16.f32 "
                        "{%0,%1,%2,%3}, {%4,%5,%6,%7}, {%8,%9}, {%0,%1,%2,%3};"
                        : "+f"(acc[mi][ni][0]), "+f"(acc[mi][ni][1]),
                          "+f"(acc[mi][ni][2]), "+f"(acc[mi][ni][3])
                        : "r"(a[mi][0]), "r"(a[mi][1]), "r"(a[mi][2]), "r"(a[mi][3]),
                          "r"(b[ni][0]), "r"(b[ni][1]));
                }
        }
    }

    // Epilogue: tanh(acc + dec_f) * v, reduce over this tile's 128 N cols.
    float pr[4][2];
#pragma unroll
    for (int mi = 0; mi < 4; ++mi) { pr[mi][0] = 0.f; pr[mi][1] = 0.f; }
#pragma unroll
    for (int mi = 0; mi < 4; ++mi)
#pragma unroll
        for (int ni = 0; ni < 4; ++ni) {
            const int col = wn * 32 + ni * 8 + tq * 2;
            const float t0 = t_s[col], t1 = t_s[col + 1];
            const float v0 = v_s[col], v1 = v_s[col + 1];
            pr[mi][0] += fast_tanh(acc[mi][ni][0] + t0) * v0
                       + fast_tanh(acc[mi][ni][1] + t1) * v1;
            pr[mi][1] += fast_tanh(acc[mi][ni][2] + t0) * v0
                       + fast_tanh(acc[mi][ni][3] + t1) * v1;
        }
#pragma unroll
    for (int mi = 0; mi < 4; ++mi)
#pragma unroll
        for (int hh = 0; hh < 2; ++hh) {
            float x = pr[mi][hh];
            x += __shfl_xor_sync(0xffffffffu, x, 1);
            x += __shfl_xor_sync(0xffffffffu, x, 2);
            pr[mi][hh] = x;
        }
    float* pe = (float*)(sm + OFF_PE);           // [4 wn][128 rows]
    __syncthreads();
    if (tq == 0) {
#pragma unroll
        for (int mi = 0; mi < 4; ++mi) {
            const int row = wm * 64 + mi * 16 + g;
            pe[wn * MT + row]     = pr[mi][0];
            pe[wn * MT + row + 8] = pr[mi][1];
        }
    }
    __syncthreads();
    if (tid < MT)
        g_pe[(size_t)nt * BS + m0 + tid] =
            pe[tid] + pe[MT + tid] + pe[2 * MT + tid] + pe[3 * MT + tid];
}

// ---------------------------------------------------------------------------
// Kernel 2: sum partials, mask, softmax over S per batch row.
// ---------------------------------------------------------------------------
__global__ void softmax_kernel(const int* __restrict__ mask,
                               float* __restrict__ attn) {
    __shared__ float e_s[Ss];
    __shared__ float red[256];
    const int b = blockIdx.x, tid = threadIdx.x;
    const size_t r0 = (size_t)b * Ss;
    for (int s = tid; s < Ss; s += 256) {
        const size_t r = r0 + s;
        float e = 0.f;
#pragma unroll
        for (int c = 0; c < NTILES; ++c) e += g_pe[(size_t)c * BS + r];
        if (mask[r] == 0) e = -1e10f;
        e_s[s] = e;
    }
    __syncthreads();
    float m = -INFINITY;
    for (int s = tid; s < Ss; s += 256) m = fmaxf(m, e_s[s]);
    red[tid] = m; __syncthreads();
    for (int o = 128; o > 0; o >>= 1) {
        if (tid < o) red[tid] = fmaxf(red[tid], red[tid + o]);
        __syncthreads();
    }
    const float rowmax = red[0]; __syncthreads();
    float lsum = 0.f;
    for (int s = tid; s < Ss; s += 256) {
        const float ex = expf(e_s[s] - rowmax);
        e_s[s] = ex; lsum += ex;
    }
    red[tid] = lsum; __syncthreads();
    for (int o = 128; o > 0; o >>= 1) {
        if (tid < o) red[tid] += red[tid + o];
        __syncthreads();
    }
    const float inv = 1.0f / red[0];
    for (int s = tid; s < Ss; s += 256) attn[r0 + s] = e_s[s] * inv;
}

// ---------------------------------------------------------------------------
// Kernel 3: context[b,e] = sum_s attn[b,s] * Eh[b,s,e]  (fp16 E copy; HBM-bound)
// ---------------------------------------------------------------------------
__global__ void context_kernel(const float* __restrict__ attn,
                               float* __restrict__ ctx) {
    __shared__ float w_s[Ss];
    const int b = blockIdx.y;
    const int e = (blockIdx.x * 256 + threadIdx.x) * 2;
    for (int s = threadIdx.x; s < Ss; s += 256) w_s[s] = attn[(size_t)b * Ss + s];
    __syncthreads();
    const __half* Eb = g_Eh + (size_t)b * Ss * Kk;
    float ax = 0.f, ay = 0.f, bx = 0.f, by = 0.f;
    for (int s = 0; s < Ss; s += 2) {
        const float w0 = w_s[s], w1 = w_s[s + 1];
        float2 f0 = __half22float2(*reinterpret_cast<const __half2*>(
            &Eb[(size_t)s * Kk + e]));
        float2 f1 = __half22float2(*reinterpret_cast<const __half2*>(
            &Eb[(size_t)(s + 1) * Kk + e]));
        ax += w0 * f0.x; ay += w0 * f0.y;
        bx += w1 * f1.x; by += w1 * f1.y;
    }
    ctx[(size_t)b * Kk + e]     = ax + bx;
    ctx[(size_t)b * Kk + e + 1] = ay + by;
}

// ---------------------------------------------------------------------------
extern "C" void kernel_launch(void* const* d_in, const int* in_sizes, int n_in,
                              void* d_out, int out_size) {
    const float* dh   = (const float*)d_in[0];
    const float* E    = (const float*)d_in[1];
    const int*   mask = (const int*)d_in[2];
    const float* Wh   = (const float*)d_in[3];
    const float* Ws   = (const float*)d_in[4];
    const float* v    = (const float*)d_in[5];

    float* out  = (float*)d_out;
    float* ctx  = out;                        // [B, 2H]
    float* attn = out + (size_t)Bb * Kk;      // [B, S]

    // Idempotent, non-stream host call: safe under graph capture, no static guard.
    cudaFuncSetAttribute(energy_kernel,
                         cudaFuncAttributeMaxDynamicSharedMemorySize, SM_TOTAL);

    decf_kernel<<<dim3(Hh / 128, Bb), 128>>>(dh, Wh);
    cvt_ws_kernel<<<(Kk * Hh / 4) / 256, 256>>>(Ws);
    cvt_e_kernel<<<(int)(((size_t)BS * Kk / 4) / 256), 256>>>(E);
    energy_kernel<<<dim3(NTILES, BS / MT), 256, SM_TOTAL>>>(v);
    softmax_kernel<<<Bb, 256>>>(mask, attn);
    context_kernel<<<dim3(Kk / 512, Bb), 256>>>(attn, ctx);
}

// round 12
// speedup vs baseline: 1.0617x; 1.0617x over previous
#include <cuda_runtime.h>
#include <cuda_fp16.h>
#include <cstdint>
#include <cstddef>

// ---------------------------------------------------------------------------
// Problem constants
// ---------------------------------------------------------------------------
constexpr int Bb = 64;
constexpr int Ss = 2048;
constexpr int Hh = 1024;
constexpr int Kk = 2048;          // 2H reduction dim
constexpr int BS = Bb * Ss;       // 131072 rows
constexpr int MT = 128;           // CTA M tile
constexpr int NT = 256;           // CTA N tile
constexpr int NTILES = Hh / NT;   // 4
constexpr int KCH = 32;           // K chunk (halves)
constexpr int NCH = Kk / KCH;     // 64 chunks
constexpr int STAGES = 5;

constexpr int NTHREADS = 288;     // 8 consumer warps + 1 producer warp

// Padded smem strides (halves) — rows ≡ 16 mod 128 bytes: conflict-free ldmatrix
constexpr int ASTR = KCH + 8;     // 40 halves = 80B rows
constexpr int BSTR = NT + 8;      // 264 halves = 528B rows
constexpr int ABYTES = MT * ASTR * 2;    // 10240 per stage
constexpr int BBYTES = KCH * BSTR * 2;   // 16896 per stage

// Dynamic smem layout (bytes)
constexpr int OFF_A = 0;                              // 5 x 10240 = 51200
constexpr int OFF_B = OFF_A + STAGES * ABYTES;        // 51200, 5 x 16896 = 84480
constexpr int OFF_T = OFF_B + STAGES * BBYTES;        // 135680
constexpr int OFF_V = OFF_T + NT * 4;                 // 136704
constexpr int OFF_PE = OFF_V + NT * 4;                // 137728
constexpr int OFF_MB = OFF_PE + 4 * MT * 4;           // 139776 (full[5], empty[5])
constexpr int SM_TOTAL = OFF_MB + 2 * STAGES * 8;     // 139856

// Scratch (__device__ globals: allocation-free contract)
__device__ float  g_decf[Bb * Hh];
__device__ float  g_pe[NTILES * BS];
__device__ __half g_Wsh[(size_t)Kk * Hh];          // Ws in fp16, [K][H]
__device__ __half g_Eh[(size_t)BS * Kk];           // E in fp16,  [BS][2H]

__device__ __forceinline__ float fast_tanh(float x) {
    float y; asm("tanh.approx.f32 %0, %1;" : "=f"(y) : "f"(x)); return y;
}
__device__ __forceinline__ uint32_t elect_one() {
    uint32_t p;
    asm volatile("{\n\t.reg .pred p;\n\telect.sync _|p, 0xFFFFFFFF;\n\t"
                 "selp.b32 %0, 1, 0, p;\n\t}" : "=r"(p));
    return p;
}
__device__ __forceinline__ void mbar_init(uint32_t a, uint32_t cnt) {
    asm volatile("mbarrier.init.shared.b64 [%0], %1;" :: "r"(a), "r"(cnt) : "memory");
}
__device__ __forceinline__ void mbar_arrive(uint32_t a) {
    asm volatile("mbarrier.arrive.shared.b64 _, [%0];" :: "r"(a) : "memory");
}
__device__ __forceinline__ void mbar_wait(uint32_t a, uint32_t parity) {
    asm volatile("{\n\t.reg .pred P;\n\tWL_%=:\n\t"
                 "mbarrier.try_wait.parity.acquire.cta.shared::cta.b64 P, [%0], %1, 0x989680;\n\t"
                 "@P bra.uni WD_%=;\n\tbra.uni WL_%=;\n\tWD_%=:\n\t}"
                 :: "r"(a), "r"(parity) : "memory");
}

// ---------------------------------------------------------------------------
// Kernel 0: dec_f = dh @ Wh
// ---------------------------------------------------------------------------
__global__ void decf_kernel(const float* __restrict__ dh,
                            const float* __restrict__ Wh) {
    __shared__ float dh_s[Hh];
    const int b = blockIdx.y;
    const int k = blockIdx.x * 128 + threadIdx.x;
    for (int h = threadIdx.x; h < Hh; h += 128) dh_s[h] = dh[b * Hh + h];
    __syncthreads();
    float acc = 0.f;
#pragma unroll 8
    for (int h = 0; h < Hh; ++h) acc += dh_s[h] * Wh[h * Hh + k];
    g_decf[b * Hh + k] = acc;
}

// ---------------------------------------------------------------------------
// Kernel 0b/0c: fp32 -> fp16 elementwise converts (memory-bound)
// ---------------------------------------------------------------------------
__global__ void cvt_ws_kernel(const float* __restrict__ Ws) {
    const size_t i4 = (size_t)blockIdx.x * 256 + threadIdx.x;
    float4 f = reinterpret_cast<const float4*>(Ws)[i4];
    __half2 h0 = __floats2half2_rn(f.x, f.y);
    __half2 h1 = __floats2half2_rn(f.z, f.w);
    uint2 u; u.x = *(uint32_t*)&h0; u.y = *(uint32_t*)&h1;
    reinterpret_cast<uint2*>(g_Wsh)[i4] = u;
}
__global__ void cvt_e_kernel(const float* __restrict__ E) {
    const size_t i4 = (size_t)blockIdx.x * 256 + threadIdx.x;
    float4 f = reinterpret_cast<const float4*>(E)[i4];
    __half2 h0 = __floats2half2_rn(f.x, f.y);
    __half2 h1 = __floats2half2_rn(f.z, f.w);
    uint2 u; u.x = *(uint32_t*)&h0; u.y = *(uint32_t*)&h1;
    reinterpret_cast<uint2*>(g_Eh)[i4] = u;
}

// ---------------------------------------------------------------------------
// Kernel 1: fused energy GEMM — warp-specialized producer/consumer pipeline.
//   acc[128,256] = Eh_tile @ Wsh_tile (K=2048, fp32 acc), warp tile 64x64.
//   8 consumer warps (MMA) + 1 producer warp (cp.async), 5-stage mbarrier ring.
//   partial_energy[row] = sum_n tanh(acc + dec_f) * v   -> g_pe[ntile]
// ---------------------------------------------------------------------------
__global__ __launch_bounds__(NTHREADS, 1)
void energy_kernel(const float* __restrict__ v) {
    extern __shared__ char sm[];
    const uint32_t sb = (uint32_t)__cvta_generic_to_shared(sm);
    const int tid = threadIdx.x, wid = tid >> 5, lane = tid & 31;
    const int wm = wid >> 2, wn = wid & 3;       // consumer warp grid 2x4 (64x64)
    const int g = lane >> 2, tq = lane & 3;
    const int nt = blockIdx.x;                   // 0..3 fastest: L2 reuse of A
    const int m0 = blockIdx.y * MT;
    const int n0 = nt * NT;
    const int batch = m0 >> 11;                  // m0 / Ss

    const uint32_t mb_full  = sb + OFF_MB;            // full[s]  = +8*s
    const uint32_t mb_empty = sb + OFF_MB + STAGES*8; // empty[s] = +8*s

    if (tid == 0) {
#pragma unroll
        for (int s = 0; s < STAGES; ++s) {
            mbar_init(mb_full + 8 * s, 32);   // producer warp: 32 async-arrives
            mbar_init(mb_empty + 8 * s, 8);   // 8 consumer warps: 1 arrive each
        }
    }
    float* t_s = (float*)(sm + OFF_T);
    float* v_s = (float*)(sm + OFF_V);
    if (tid < NT) {
        t_s[tid] = g_decf[batch * Hh + n0 + tid];
        v_s[tid] = v[n0 + tid];
    }
    __syncthreads();

    float acc[4][8][4];
#pragma unroll
    for (int i = 0; i < 4; ++i)
#pragma unroll
        for (int j = 0; j < 8; ++j)
#pragma unroll
            for (int q = 0; q < 4; ++q) acc[i][j][q] = 0.f;

    if (wid == 8) {
        // ---------------- producer warp ----------------
        int st = 0, ph = 1;                       // fresh barrier: parity-1 passes
        for (int c = 0; c < NCH; ++c) {
            const int kc = c * KCH;
            mbar_wait(mb_empty + 8 * st, ph);
            const uint32_t ab = sb + OFF_A + st * ABYTES;
#pragma unroll
            for (int j = 0; j < 16; ++j) {        // A: 512 x 16B
                const int c16 = lane + j * 32;
                const int row = c16 >> 2, o = c16 & 3;
                const uint32_t dst = ab + row * 80 + o * 16;
                const __half* src = &g_Eh[(size_t)(m0 + row) * Kk + kc + o * 8];
                asm volatile("cp.async.cg.shared.global [%0], [%1], 16;"
                             :: "r"(dst), "l"(src) : "memory");
            }
            const uint32_t bb = sb + OFF_B + st * BBYTES;
#pragma unroll
            for (int j = 0; j < 32; ++j) {        // B: 1024 x 16B
                const int c16 = lane + j * 32;
                const int kr = c16 >> 5, o = c16 & 31;
                const uint32_t dst = bb + kr * 528 + o * 16;
                const __half* src = &g_Wsh[(size_t)(kc + kr) * Hh + n0 + o * 8];
                asm volatile("cp.async.cg.shared.global [%0], [%1], 16;"
                             :: "r"(dst), "l"(src) : "memory");
            }
            asm volatile("cp.async.mbarrier.arrive.noinc.shared::cta.b64 [%0];"
                         :: "r"(mb_full + 8 * st) : "memory");
            if (++st == STAGES) { st = 0; ph ^= 1; }
        }
    } else {
        // ---------------- consumer warps ----------------
        int st = 0, ph = 0;
        for (int c = 0; c < NCH; ++c) {
            mbar_wait(mb_full + 8 * st, ph);
            const uint32_t ab = sb + OFF_A + st * ABYTES;
            const uint32_t bb = sb + OFF_B + st * BBYTES;
#pragma unroll
            for (int ks = 0; ks < 2; ++ks) {
                const int k0 = ks * 16;
                uint32_t a[4][4], b[8][2];
#pragma unroll
                for (int mi = 0; mi < 4; ++mi) {
                    const uint32_t addr = ab + (wm * 64 + mi * 16 + (lane & 15)) * 80
                                        + (k0 + (lane >> 4) * 8) * 2;
                    asm volatile(
                        "ldmatrix.sync.aligned.m8n8.x4.shared.b16 {%0,%1,%2,%3}, [%4];"
                        : "=r"(a[mi][0]), "=r"(a[mi][1]), "=r"(a[mi][2]), "=r"(a[mi][3])
                        : "r"(addr));
                }
#pragma unroll
                for (int np = 0; np < 4; ++np) {  // 2 n-octets per x4.trans
                    const uint32_t addr = bb + (k0 + (lane & 15)) * 528
                                        + (wn * 64 + np * 16 + (lane >> 4) * 8) * 2;
                    asm volatile(
                        "ldmatrix.sync.aligned.m8n8.x4.trans.shared.b16 {%0,%1,%2,%3}, [%4];"
                        : "=r"(b[2 * np][0]), "=r"(b[2 * np][1]),
                          "=r"(b[2 * np + 1][0]), "=r"(b[2 * np + 1][1])
                        : "r"(addr));
                }
#pragma unroll
                for (int mi = 0; mi < 4; ++mi)
#pragma unroll
                    for (int ni = 0; ni < 8; ++ni) {
                        asm volatile(
                            "mma.sync.aligned.m16n8k16.row.col.f32.f16.f16.f32 "
                            "{%0,%1,%2,%3}, {%4,%5,%6,%7}, {%8,%9}, {%0,%1,%2,%3};"
                            : "+f"(acc[mi][ni][0]), "+f"(acc[mi][ni][1]),
                              "+f"(acc[mi][ni][2]), "+f"(acc[mi][ni][3])
                            : "r"(a[mi][0]), "r"(a[mi][1]), "r"(a[mi][2]), "r"(a[mi][3]),
                              "r"(b[ni][0]), "r"(b[ni][1]));
                    }
            }
            if (elect_one()) mbar_arrive(mb_empty + 8 * st);
            if (++st == STAGES) { st = 0; ph ^= 1; }
        }
    }

    // Epilogue: tanh(acc + dec_f) * v, reduce over this tile's 256 N cols.
    float pr[4][2];
#pragma unroll
    for (int mi = 0; mi < 4; ++mi) { pr[mi][0] = 0.f; pr[mi][1] = 0.f; }
    if (wid < 8) {
#pragma unroll
        for (int mi = 0; mi < 4; ++mi)
#pragma unroll
            for (int ni = 0; ni < 8; ++ni) {
                const int col = wn * 64 + ni * 8 + tq * 2;
                const float t0 = t_s[col], t1 = t_s[col + 1];
                const float v0 = v_s[col], v1 = v_s[col + 1];
                pr[mi][0] += fast_tanh(acc[mi][ni][0] + t0) * v0
                           + fast_tanh(acc[mi][ni][1] + t1) * v1;
                pr[mi][1] += fast_tanh(acc[mi][ni][2] + t0) * v0
                           + fast_tanh(acc[mi][ni][3] + t1) * v1;
            }
#pragma unroll
        for (int mi = 0; mi < 4; ++mi)
#pragma unroll
            for (int hh = 0; hh < 2; ++hh) {
                float x = pr[mi][hh];
                x += __shfl_xor_sync(0xffffffffu, x, 1);
                x += __shfl_xor_sync(0xffffffffu, x, 2);
                pr[mi][hh] = x;
            }
    }
    float* pe = (float*)(sm + OFF_PE);           // [4 wn][128 rows]
    __syncthreads();
    if (wid < 8 && tq == 0) {
#pragma unroll
        for (int mi = 0; mi < 4; ++mi) {
            const int row = wm * 64 + mi * 16 + g;
            pe[wn * MT + row]     = pr[mi][0];
            pe[wn * MT + row + 8] = pr[mi][1];
        }
    }
    __syncthreads();
    if (tid < MT)
        g_pe[(size_t)nt * BS + m0 + tid] =
            pe[tid] + pe[MT + tid] + pe[2 * MT + tid] + pe[3 * MT + tid];
}

// ---------------------------------------------------------------------------
// Kernel 2: sum partials, mask, softmax over S per batch row.
// ---------------------------------------------------------------------------
__global__ void softmax_kernel(const int* __restrict__ mask,
                               float* __restrict__ attn) {
    __shared__ float e_s[Ss];
    __shared__ float red[256];
    const int b = blockIdx.x, tid = threadIdx.x;
    const size_t r0 = (size_t)b * Ss;
    for (int s = tid; s < Ss; s += 256) {
        const size_t r = r0 + s;
        float e = 0.f;
#pragma unroll
        for (int c = 0; c < NTILES; ++c) e += g_pe[(size_t)c * BS + r];
        if (mask[r] == 0) e = -1e10f;
        e_s[s] = e;
    }
    __syncthreads();
    float m = -INFINITY;
    for (int s = tid; s < Ss; s += 256) m = fmaxf(m, e_s[s]);
    red[tid] = m; __syncthreads();
    for (int o = 128; o > 0; o >>= 1) {
        if (tid < o) red[tid] = fmaxf(red[tid], red[tid + o]);
        __syncthreads();
    }
    const float rowmax = red[0]; __syncthreads();
    float lsum = 0.f;
    for (int s = tid; s < Ss; s += 256) {
        const float ex = expf(e_s[s] - rowmax);
        e_s[s] = ex; lsum += ex;
    }
    red[tid] = lsum; __syncthreads();
    for (int o = 128; o > 0; o >>= 1) {
        if (tid < o) red[tid] += red[tid + o];
        __syncthreads();
    }
    const float inv = 1.0f / red[0];
    for (int s = tid; s < Ss; s += 256) attn[r0 + s] = e_s[s] * inv;
}

// ---------------------------------------------------------------------------
// Kernel 3: context[b,e] = sum_s attn[b,s] * Eh[b,s,e]  (fp16 E copy; HBM-bound)
// ---------------------------------------------------------------------------
__global__ void context_kernel(const float* __restrict__ attn,
                               float* __restrict__ ctx) {
    __shared__ float w_s[Ss];
    const int b = blockIdx.y;
    const int e = (blockIdx.x * 256 + threadIdx.x) * 2;
    for (int s = threadIdx.x; s < Ss; s += 256) w_s[s] = attn[(size_t)b * Ss + s];
    __syncthreads();
    const __half* Eb = g_Eh + (size_t)b * Ss * Kk;
    float ax = 0.f, ay = 0.f, bx = 0.f, by = 0.f;
    for (int s = 0; s < Ss; s += 2) {
        const float w0 = w_s[s], w1 = w_s[s + 1];
        float2 f0 = __half22float2(*reinterpret_cast<const __half2*>(
            &Eb[(size_t)s * Kk + e]));
        float2 f1 = __half22float2(*reinterpret_cast<const __half2*>(
            &Eb[(size_t)(s + 1) * Kk + e]));
        ax += w0 * f0.x; ay += w0 * f0.y;
        bx += w1 * f1.x; by += w1 * f1.y;
    }
    ctx[(size_t)b * Kk + e]     = ax + bx;
    ctx[(size_t)b * Kk + e + 1] = ay + by;
}

// ---------------------------------------------------------------------------
extern "C" void kernel_launch(void* const* d_in, const int* in_sizes, int n_in,
                              void* d_out, int out_size) {
    const float* dh   = (const float*)d_in[0];
    const float* E    = (const float*)d_in[1];
    const int*   mask = (const int*)d_in[2];
    const float* Wh   = (const float*)d_in[3];
    const float* Ws   = (const float*)d_in[4];
    const float* v    = (const float*)d_in[5];

    float* out  = (float*)d_out;
    float* ctx  = out;                        // [B, 2H]
    float* attn = out + (size_t)Bb * Kk;      // [B, S]

    // Idempotent, non-stream host call: safe under graph capture, no static guard.
    cudaFuncSetAttribute(energy_kernel,
                         cudaFuncAttributeMaxDynamicSharedMemorySize, SM_TOTAL);

    decf_kernel<<<dim3(Hh / 128, Bb), 128>>>(dh, Wh);
    cvt_ws_kernel<<<(Kk * Hh / 4) / 256, 256>>>(Ws);
    cvt_e_kernel<<<(int)(((size_t)BS * Kk / 4) / 256), 256>>>(E);
    energy_kernel<<<dim3(NTILES, BS / MT), NTHREADS, SM_TOTAL>>>(v);
    softmax_kernel<<<Bb, 256>>>(mask, attn);
    context_kernel<<<dim3(Kk / 512, Bb), 256>>>(attn, ctx);
}

// round 15
// speedup vs baseline: 1.4019x; 1.3204x over previous
#include <cuda_runtime.h>
#include <cuda_fp16.h>
#include <cstdint>
#include <cstddef>

// ---------------------------------------------------------------------------
// Problem constants
// ---------------------------------------------------------------------------
constexpr int Bb = 64;
constexpr int Ss = 2048;
constexpr int Hh = 1024;
constexpr int Kk = 2048;          // 2H reduction dim
constexpr int BS = Bb * Ss;       // 131072 rows
constexpr int MT = 128;           // CTA M tile
constexpr int NT = 256;           // CTA N tile
constexpr int NTILES = Hh / NT;   // 4
constexpr int KCH = 32;           // K chunk (halves)
constexpr int NCH = Kk / KCH;     // 64 chunks
constexpr int STAGES = 5;

// Padded smem strides (halves) — rows ≡ 16 mod 128 bytes: conflict-free ldmatrix
constexpr int ASTR = KCH + 8;     // 40 halves = 80B rows
constexpr int BSTR = NT + 8;      // 264 halves = 528B rows
constexpr int ABYTES = MT * ASTR * 2;    // 10240 per stage
constexpr int BBYTES = KCH * BSTR * 2;   // 16896 per stage

// Dynamic smem layout (bytes)
constexpr int OFF_A = 0;                              // 5 x 10240 = 51200
constexpr int OFF_B = OFF_A + STAGES * ABYTES;        // 5 x 16896 = 84480
constexpr int OFF_T = OFF_B + STAGES * BBYTES;        // 135680
constexpr int OFF_V = OFF_T + NT * 4;                 // 136704
constexpr int OFF_PE = OFF_V + NT * 4;                // 137728
constexpr int SM_TOTAL = OFF_PE + 4 * MT * 4;         // 139776

// Scratch (__device__ globals: allocation-free contract)
__device__ float  g_decf[Bb * Hh];
__device__ float  g_pe[NTILES * BS];
__device__ __half g_Wsh[(size_t)Kk * Hh];          // Ws in fp16, [K][H]
__device__ __half g_Eh[(size_t)BS * Kk];           // E in fp16,  [BS][2H]

__device__ __forceinline__ float fast_tanh(float x) {
    float y; asm("tanh.approx.f32 %0, %1;" : "=f"(y) : "f"(x)); return y;
}

// ---------------------------------------------------------------------------
// Kernel 0: dec_f = dh @ Wh
// ---------------------------------------------------------------------------
__global__ void decf_kernel(const float* __restrict__ dh,
                            const float* __restrict__ Wh) {
    __shared__ float dh_s[Hh];
    const int b = blockIdx.y;
    const int k = blockIdx.x * 128 + threadIdx.x;
    for (int h = threadIdx.x; h < Hh; h += 128) dh_s[h] = dh[b * Hh + h];
    __syncthreads();
    float acc = 0.f;
#pragma unroll 8
    for (int h = 0; h < Hh; ++h) acc += dh_s[h] * Wh[h * Hh + k];
    g_decf[b * Hh + k] = acc;
}

// ---------------------------------------------------------------------------
// Kernel 0b/0c: fp32 -> fp16 elementwise converts (memory-bound)
// ---------------------------------------------------------------------------
__global__ void cvt_ws_kernel(const float* __restrict__ Ws) {
    const size_t i4 = (size_t)blockIdx.x * 256 + threadIdx.x;
    float4 f = reinterpret_cast<const float4*>(Ws)[i4];
    __half2 h0 = __floats2half2_rn(f.x, f.y);
    __half2 h1 = __floats2half2_rn(f.z, f.w);
    uint2 u; u.x = *(uint32_t*)&h0; u.y = *(uint32_t*)&h1;
    reinterpret_cast<uint2*>(g_Wsh)[i4] = u;
}
__global__ void cvt_e_kernel(const float* __restrict__ E) {
    const size_t i4 = (size_t)blockIdx.x * 256 + threadIdx.x;
    float4 f = reinterpret_cast<const float4*>(E)[i4];
    __half2 h0 = __floats2half2_rn(f.x, f.y);
    __half2 h1 = __floats2half2_rn(f.z, f.w);
    uint2 u; u.x = *(uint32_t*)&h0; u.y = *(uint32_t*)&h1;
    reinterpret_cast<uint2*>(g_Eh)[i4] = u;
}

// ---------------------------------------------------------------------------
// Kernel 1: fused energy GEMM — 5-stage cp.async ring + cross-chunk register
//   fragment prefetch (LDSM always overlapped with MMA, incl. across BAR).
//   acc[128,256] = Eh_tile @ Wsh_tile (K=2048, fp32 acc), warp tile 64x64.
//   partial_energy[row] = sum_n tanh(acc + dec_f) * v   -> g_pe[ntile]
// ---------------------------------------------------------------------------
__global__ __launch_bounds__(256, 1)
void energy_kernel(const float* __restrict__ v) {
    extern __shared__ char sm[];
    const uint32_t sb = (uint32_t)__cvta_generic_to_shared(sm);
    const int tid = threadIdx.x, wid = tid >> 5, lane = tid & 31;
    const int wm = wid >> 2, wn = wid & 3;       // warp grid 2x4, tile 64x64
    const int g = lane >> 2, tq = lane & 3;
    const int nt = blockIdx.x;                   // 0..3 fastest: L2 reuse of A
    const int m0 = blockIdx.y * MT;
    const int n0 = nt * NT;
    const int batch = m0 >> 11;                  // m0 / Ss

    float* t_s = (float*)(sm + OFF_T);
    float* v_s = (float*)(sm + OFF_V);
    if (tid < NT) {
        t_s[tid] = g_decf[batch * Hh + n0 + tid];
        v_s[tid] = v[n0 + tid];
    }

    float acc[4][8][4];
#pragma unroll
    for (int i = 0; i < 4; ++i)
#pragma unroll
        for (int j = 0; j < 8; ++j)
#pragma unroll
            for (int q = 0; q < 4; ++q) acc[i][j][q] = 0.f;

    auto load_stage = [&](int st, int kc) {
        const uint32_t ab = sb + OFF_A + st * ABYTES;
#pragma unroll
        for (int i = 0; i < 2; ++i) {            // A: 512 x 16B chunks
            const int c = tid + i * 256;
            const int row = c >> 2, o = c & 3;
            const uint32_t dst = ab + row * 80 + o * 16;
            const __half* src = &g_Eh[(size_t)(m0 + row) * Kk + kc + o * 8];
            asm volatile("cp.async.cg.shared.global [%0], [%1], 16;"
                         :: "r"(dst), "l"(src) : "memory");
        }
        const uint32_t bb = sb + OFF_B + st * BBYTES;
#pragma unroll
        for (int i = 0; i < 4; ++i) {            // B: 1024 x 16B chunks
            const int c = tid + i * 256;
            const int kr = c >> 5, o = c & 31;
            const uint32_t dst = bb + kr * 528 + o * 16;
            const __half* src = &g_Wsh[(size_t)(kc + kr) * Hh + n0 + o * 8];
            asm volatile("cp.async.cg.shared.global [%0], [%1], 16;"
                         :: "r"(dst), "l"(src) : "memory");
        }
        asm volatile("cp.async.commit_group;" ::: "memory");
    };

    // Fragment loaders (k0 = 0 or 16 within a stage)
    auto ld_a = [&](uint32_t a[4][4], int st, int k0) {
        const uint32_t ab = sb + OFF_A + st * ABYTES;
#pragma unroll
        for (int mi = 0; mi < 4; ++mi) {
            const uint32_t addr = ab + (wm * 64 + mi * 16 + (lane & 15)) * 80
                                + (k0 + (lane >> 4) * 8) * 2;
            asm volatile(
                "ldmatrix.sync.aligned.m8n8.x4.shared.b16 {%0,%1,%2,%3}, [%4];"
                : "=r"(a[mi][0]), "=r"(a[mi][1]), "=r"(a[mi][2]), "=r"(a[mi][3])
                : "r"(addr));
        }
    };
    auto ld_b = [&](uint32_t b[8][2], int st, int k0) {
        const uint32_t bb = sb + OFF_B + st * BBYTES;
#pragma unroll
        for (int np = 0; np < 4; ++np) {
            const uint32_t addr = bb + (k0 + (lane & 15)) * 528
                                + (wn * 64 + np * 16 + (lane >> 4) * 8) * 2;
            asm volatile(
                "ldmatrix.sync.aligned.m8n8.x4.trans.shared.b16 {%0,%1,%2,%3}, [%4];"
                : "=r"(b[2 * np][0]), "=r"(b[2 * np][1]),
                  "=r"(b[2 * np + 1][0]), "=r"(b[2 * np + 1][1])
                : "r"(addr));
        }
    };
    auto mma_block = [&](uint32_t a[4][4], uint32_t b[8][2]) {
#pragma unroll
        for (int mi = 0; mi < 4; ++mi)
#pragma unroll
            for (int ni = 0; ni < 8; ++ni) {
                asm volatile(
                    "mma.sync.aligned.m16n8k16.row.col.f32.f16.f16.f32 "
                    "{%0,%1,%2,%3}, {%4,%5,%6,%7}, {%8,%9}, {%0,%1,%2,%3};"
                    : "+f"(acc[mi][ni][0]), "+f"(acc[mi][ni][1]),
                      "+f"(acc[mi][ni][2]), "+f"(acc[mi][ni][3])
                    : "r"(a[mi][0]), "r"(a[mi][1]), "r"(a[mi][2]), "r"(a[mi][3]),
                      "r"(b[ni][0]), "r"(b[ni][1]));
            }
    };

    // Preload 4 stages; after wait_group 2, groups 0 and 1 are complete.
#pragma unroll
    for (int s = 0; s < 4; ++s) load_stage(s, s * KCH);
    asm volatile("cp.async.wait_group 2;" ::: "memory");
    __syncthreads();

    uint32_t a0[4][4], b0[8][2], a1[4][4], b1[8][2];
    ld_a(a0, 0, 0);
    ld_b(b0, 0, 0);

    for (int c = 0; c < NCH; ++c) {
        const int st = c % STAGES;
        if (c + 4 < NCH) load_stage((c + 4) % STAGES, (c + 4) * KCH);

        // ks=0: prefetch (c, ks=1), compute with (c, ks=0)
        ld_a(a1, st, 16);
        ld_b(b1, st, 16);
        mma_block(a0, b0);

        // ks=1: prefetch (c+1, ks=0) — stage c+1 resident & visible by invariant
        if (c + 1 < NCH) {
            const int stn = (c + 1) % STAGES;
            ld_a(a0, stn, 0);
            ld_b(b0, stn, 0);
        }
        mma_block(a1, b1);

        if (c + 1 < NCH) {
            if (c + 4 < NCH) {
                asm volatile("cp.async.wait_group 2;" ::: "memory");
            } else {
                asm volatile("cp.async.wait_group 0;" ::: "memory");
            }
            __syncthreads();
        }
    }

    // Epilogue: tanh(acc + dec_f) * v, reduce over this tile's 256 N cols.
    float pr[4][2];
#pragma unroll
    for (int mi = 0; mi < 4; ++mi) { pr[mi][0] = 0.f; pr[mi][1] = 0.f; }
#pragma unroll
    for (int mi = 0; mi < 4; ++mi)
#pragma unroll
        for (int ni = 0; ni < 8; ++ni) {
            const int col = wn * 64 + ni * 8 + tq * 2;
            const float t0 = t_s[col], t1 = t_s[col + 1];
            const float v0 = v_s[col], v1 = v_s[col + 1];
            pr[mi][0] += fast_tanh(acc[mi][ni][0] + t0) * v0
                       + fast_tanh(acc[mi][ni][1] + t1) * v1;
            pr[mi][1] += fast_tanh(acc[mi][ni][2] + t0) * v0
                       + fast_tanh(acc[mi][ni][3] + t1) * v1;
        }
#pragma unroll
    for (int mi = 0; mi < 4; ++mi)
#pragma unroll
        for (int hh = 0; hh < 2; ++hh) {
            float x = pr[mi][hh];
            x += __shfl_xor_sync(0xffffffffu, x, 1);
            x += __shfl_xor_sync(0xffffffffu, x, 2);
            pr[mi][hh] = x;
        }
    float* pe = (float*)(sm + OFF_PE);           // [4 wn][128 rows]
    __syncthreads();
    if (tq == 0) {
#pragma unroll
        for (int mi = 0; mi < 4; ++mi) {
            const int row = wm * 64 + mi * 16 + g;
            pe[wn * MT + row]     = pr[mi][0];
            pe[wn * MT + row + 8] = pr[mi][1];
        }
    }
    __syncthreads();
    if (tid < MT)
        g_pe[(size_t)nt * BS + m0 + tid] =
            pe[tid] + pe[MT + tid] + pe[2 * MT + tid] + pe[3 * MT + tid];
}

// ---------------------------------------------------------------------------
// Kernel 2: sum partials, mask, softmax over S per batch row.
// ---------------------------------------------------------------------------
__global__ void softmax_kernel(const int* __restrict__ mask,
                               float* __restrict__ attn) {
    __shared__ float e_s[Ss];
    __shared__ float red[256];
    const int b = blockIdx.x, tid = threadIdx.x;
    const size_t r0 = (size_t)b * Ss;
    for (int s = tid; s < Ss; s += 256) {
        const size_t r = r0 + s;
        float e = 0.f;
#pragma unroll
        for (int c = 0; c < NTILES; ++c) e += g_pe[(size_t)c * BS + r];
        if (mask[r] == 0) e = -1e10f;
        e_s[s] = e;
    }
    __syncthreads();
    float m = -INFINITY;
    for (int s = tid; s < Ss; s += 256) m = fmaxf(m, e_s[s]);
    red[tid] = m; __syncthreads();
    for (int o = 128; o > 0; o >>= 1) {
        if (tid < o) red[tid] = fmaxf(red[tid], red[tid + o]);
        __syncthreads();
    }
    const float rowmax = red[0]; __syncthreads();
    float lsum = 0.f;
    for (int s = tid; s < Ss; s += 256) {
        const float ex = expf(e_s[s] - rowmax);
        e_s[s] = ex; lsum += ex;
    }
    red[tid] = lsum; __syncthreads();
    for (int o = 128; o > 0; o >>= 1) {
        if (tid < o) red[tid] += red[tid + o];
        __syncthreads();
    }
    const float inv = 1.0f / red[0];
    for (int s = tid; s < Ss; s += 256) attn[r0 + s] = e_s[s] * inv;
}

// ---------------------------------------------------------------------------
// Kernel 3: context[b,e] = sum_s attn[b,s] * Eh[b,s,e]  (fp16 E copy; HBM-bound)
// ---------------------------------------------------------------------------
__global__ void context_kernel(const float* __restrict__ attn,
                               float* __restrict__ ctx) {
    __shared__ float w_s[Ss];
    const int b = blockIdx.y;
    const int e = (blockIdx.x * 256 + threadIdx.x) * 2;
    for (int s = threadIdx.x; s < Ss; s += 256) w_s[s] = attn[(size_t)b * Ss + s];
    __syncthreads();
    const __half* Eb = g_Eh + (size_t)b * Ss * Kk;
    float ax = 0.f, ay = 0.f, bx = 0.f, by = 0.f;
    for (int s = 0; s < Ss; s += 2) {
        const float w0 = w_s[s], w1 = w_s[s + 1];
        float2 f0 = __half22float2(*reinterpret_cast<const __half2*>(
            &Eb[(size_t)s * Kk + e]));
        float2 f1 = __half22float2(*reinterpret_cast<const __half2*>(
            &Eb[(size_t)(s + 1) * Kk + e]));
        ax += w0 * f0.x; ay += w0 * f0.y;
        bx += w1 * f1.x; by += w1 * f1.y;
    }
    ctx[(size_t)b * Kk + e]     = ax + bx;
    ctx[(size_t)b * Kk + e + 1] = ay + by;
}

// ---------------------------------------------------------------------------
extern "C" void kernel_launch(void* const* d_in, const int* in_sizes, int n_in,
                              void* d_out, int out_size) {
    const float* dh   = (const float*)d_in[0];
    const float* E    = (const float*)d_in[1];
    const int*   mask = (const int*)d_in[2];
    const float* Wh   = (const float*)d_in[3];
    const float* Ws   = (const float*)d_in[4];
    const float* v    = (const float*)d_in[5];

    float* out  = (float*)d_out;
    float* ctx  = out;                        // [B, 2H]
    float* attn = out + (size_t)Bb * Kk;      // [B, S]

    // Idempotent, non-stream host call: safe under graph capture, no static guard.
    cudaFuncSetAttribute(energy_kernel,
                         cudaFuncAttributeMaxDynamicSharedMemorySize, SM_TOTAL);

    decf_kernel<<<dim3(Hh / 128, Bb), 128>>>(dh, Wh);
    cvt_ws_kernel<<<(Kk * Hh / 4) / 256, 256>>>(Ws);
    cvt_e_kernel<<<(int)(((size_t)BS * Kk / 4) / 256), 256>>>(E);
    energy_kernel<<<dim3(NTILES, BS / MT), 256, SM_TOTAL>>>(v);
    softmax_kernel<<<Bb, 256>>>(mask, attn);
    context_kernel<<<dim3(Kk / 512, Bb), 256>>>(attn, ctx);
}

// round 16
// speedup vs baseline: 1.5669x; 1.1177x over previous
#include <cuda_runtime.h>
#include <cuda_fp16.h>
#include <cstdint>
#include <cstddef>

// ---------------------------------------------------------------------------
// Problem constants
// ---------------------------------------------------------------------------
constexpr int Bb = 64;
constexpr int Ss = 2048;
constexpr int Hh = 1024;
constexpr int Kk = 2048;          // 2H reduction dim
constexpr int BS = Bb * Ss;       // 131072 rows
constexpr int MT = 128;           // CTA M tile
constexpr int NT = 256;           // CTA N tile
constexpr int NTILES = Hh / NT;   // 4
constexpr int KCH = 32;           // K chunk (halves)
constexpr int NCH = Kk / KCH;     // 64 chunks
constexpr int STAGES = 5;

// Padded smem strides (halves) — rows ≡ 16 mod 128 bytes: conflict-free ldmatrix
constexpr int ASTR = KCH + 8;     // 40 halves = 80B rows
constexpr int BSTR = NT + 8;      // 264 halves = 528B rows
constexpr int ABYTES = MT * ASTR * 2;    // 10240 per stage
constexpr int BBYTES = KCH * BSTR * 2;   // 16896 per stage

// Dynamic smem layout (bytes)
constexpr int OFF_A = 0;                              // 5 x 10240 = 51200
constexpr int OFF_B = OFF_A + STAGES * ABYTES;        // 5 x 16896 = 84480
constexpr int OFF_T = OFF_B + STAGES * BBYTES;        // 135680
constexpr int OFF_V = OFF_T + NT * 4;                 // 136704
constexpr int OFF_PE = OFF_V + NT * 4;                // 137728
constexpr int OFF_MB = OFF_PE + 4 * MT * 4;           // 139776: full[5], empty[5]
constexpr int SM_TOTAL = OFF_MB + 2 * STAGES * 8;     // 139856

// Scratch (__device__ globals: allocation-free contract)
__device__ float  g_decf[Bb * Hh];
__device__ float  g_pe[NTILES * BS];
__device__ __half g_Wsh[(size_t)Kk * Hh];          // Ws in fp16, [K][H]
__device__ __half g_Eh[(size_t)BS * Kk];           // E in fp16,  [BS][2H]

__device__ __forceinline__ float fast_tanh(float x) {
    float y; asm("tanh.approx.f32 %0, %1;" : "=f"(y) : "f"(x)); return y;
}
__device__ __forceinline__ uint32_t elect_one() {
    uint32_t p;
    asm volatile("{\n\t.reg .pred p;\n\telect.sync _|p, 0xFFFFFFFF;\n\t"
                 "selp.b32 %0, 1, 0, p;\n\t}" : "=r"(p));
    return p;
}
__device__ __forceinline__ void mbar_init(uint32_t a, uint32_t cnt) {
    asm volatile("mbarrier.init.shared.b64 [%0], %1;" :: "r"(a), "r"(cnt) : "memory");
}
__device__ __forceinline__ void mbar_arrive(uint32_t a) {
    asm volatile("mbarrier.arrive.shared.b64 _, [%0];" :: "r"(a) : "memory");
}
__device__ __forceinline__ void mbar_wait(uint32_t a, uint32_t parity) {
    asm volatile("{\n\t.reg .pred P;\n\tWL_%=:\n\t"
                 "mbarrier.try_wait.parity.acquire.cta.shared::cta.b64 P, [%0], %1, 0x989680;\n\t"
                 "@P bra.uni WD_%=;\n\tbra.uni WL_%=;\n\tWD_%=:\n\t}"
                 :: "r"(a), "r"(parity) : "memory");
}

// ---------------------------------------------------------------------------
// Kernel 0: dec_f = dh @ Wh
// ---------------------------------------------------------------------------
__global__ void decf_kernel(const float* __restrict__ dh,
                            const float* __restrict__ Wh) {
    __shared__ float dh_s[Hh];
    const int b = blockIdx.y;
    const int k = blockIdx.x * 128 + threadIdx.x;
    for (int h = threadIdx.x; h < Hh; h += 128) dh_s[h] = dh[b * Hh + h];
    __syncthreads();
    float acc = 0.f;
#pragma unroll 8
    for (int h = 0; h < Hh; ++h) acc += dh_s[h] * Wh[h * Hh + k];
    g_decf[b * Hh + k] = acc;
}

// ---------------------------------------------------------------------------
// Kernel 0b/0c: fp32 -> fp16 elementwise converts (memory-bound)
// ---------------------------------------------------------------------------
__global__ void cvt_ws_kernel(const float* __restrict__ Ws) {
    const size_t i4 = (size_t)blockIdx.x * 256 + threadIdx.x;
    float4 f = reinterpret_cast<const float4*>(Ws)[i4];
    __half2 h0 = __floats2half2_rn(f.x, f.y);
    __half2 h1 = __floats2half2_rn(f.z, f.w);
    uint2 u; u.x = *(uint32_t*)&h0; u.y = *(uint32_t*)&h1;
    reinterpret_cast<uint2*>(g_Wsh)[i4] = u;
}
__global__ void cvt_e_kernel(const float* __restrict__ E) {
    const size_t i4 = (size_t)blockIdx.x * 256 + threadIdx.x;
    float4 f = reinterpret_cast<const float4*>(E)[i4];
    __half2 h0 = __floats2half2_rn(f.x, f.y);
    __half2 h1 = __floats2half2_rn(f.z, f.w);
    uint2 u; u.x = *(uint32_t*)&h0; u.y = *(uint32_t*)&h1;
    reinterpret_cast<uint2*>(g_Eh)[i4] = u;
}

// ---------------------------------------------------------------------------
// Kernel 1: fused energy GEMM — barrier-free mainloop. 5-stage mbarrier ring,
//   all 8 warps both load (their slice, cp.async + arrive.noinc) and consume;
//   no __syncthreads between preload and epilogue.
//   acc[128,256] = Eh_tile @ Wsh_tile (K=2048, fp32 acc), warp tile 64x64.
//   partial_energy[row] = sum_n tanh(acc + dec_f) * v   -> g_pe[ntile]
// ---------------------------------------------------------------------------
__global__ __launch_bounds__(256, 1)
void energy_kernel(const float* __restrict__ v) {
    extern __shared__ char sm[];
    const uint32_t sb = (uint32_t)__cvta_generic_to_shared(sm);
    const int tid = threadIdx.x, wid = tid >> 5, lane = tid & 31;
    const int wm = wid >> 2, wn = wid & 3;       // warp grid 2x4, tile 64x64
    const int g = lane >> 2, tq = lane & 3;
    const int nt = blockIdx.x;                   // 0..3 fastest: L2 reuse of A
    const int m0 = blockIdx.y * MT;
    const int n0 = nt * NT;
    const int batch = m0 >> 11;                  // m0 / Ss

    const uint32_t mb_full  = sb + OFF_MB;             // +8*s
    const uint32_t mb_empty = sb + OFF_MB + STAGES * 8;

    if (tid == 0) {
#pragma unroll
        for (int s = 0; s < STAGES; ++s) {
            mbar_init(mb_full + 8 * s, 256);  // one noinc arrive per thread
            mbar_init(mb_empty + 8 * s, 8);   // one arrive per warp
        }
    }
    float* t_s = (float*)(sm + OFF_T);
    float* v_s = (float*)(sm + OFF_V);
    if (tid < NT) {
        t_s[tid] = g_decf[batch * Hh + n0 + tid];
        v_s[tid] = v[n0 + tid];
    }
    __syncthreads();   // mbarriers + t_s/v_s visible

    float acc[4][8][4];
#pragma unroll
    for (int i = 0; i < 4; ++i)
#pragma unroll
        for (int j = 0; j < 8; ++j)
#pragma unroll
            for (int q = 0; q < 4; ++q) acc[i][j][q] = 0.f;

    // Each thread loads its fixed slice of a stage, then signals via noinc.
    auto load_slice = [&](int st, int kc) {
        const uint32_t ab = sb + OFF_A + st * ABYTES;
#pragma unroll
        for (int i = 0; i < 2; ++i) {            // A: 512 x 16B chunks
            const int c = tid + i * 256;
            const int row = c >> 2, o = c & 3;
            const uint32_t dst = ab + row * 80 + o * 16;
            const __half* src = &g_Eh[(size_t)(m0 + row) * Kk + kc + o * 8];
            asm volatile("cp.async.cg.shared.global [%0], [%1], 16;"
                         :: "r"(dst), "l"(src) : "memory");
        }
        const uint32_t bb = sb + OFF_B + st * BBYTES;
#pragma unroll
        for (int i = 0; i < 4; ++i) {            // B: 1024 x 16B chunks
            const int c = tid + i * 256;
            const int kr = c >> 5, o = c & 31;
            const uint32_t dst = bb + kr * 528 + o * 16;
            const __half* src = &g_Wsh[(size_t)(kc + kr) * Hh + n0 + o * 8];
            asm volatile("cp.async.cg.shared.global [%0], [%1], 16;"
                         :: "r"(dst), "l"(src) : "memory");
        }
        asm volatile("cp.async.mbarrier.arrive.noinc.shared::cta.b64 [%0];"
                     :: "r"(mb_full + 8 * st) : "memory");
    };

    // Preload 4 stages (slots 0..3).
#pragma unroll
    for (int s = 0; s < 4; ++s) load_slice(s, s * KCH);

    int stc = 0, phc = 0;    // consumer cursor over full[]
    int ste = 0, phe = 0;    // producer cursor over empty[] (refills r >= 5)

    for (int c = 0; c < NCH; ++c) {
        const int r = c + 4;                      // refill index
        if (r < NCH) {
            if (r >= STAGES) {                    // slot was consumed before
                mbar_wait(mb_empty + 8 * ste, phe);
                if (++ste == STAGES) { ste = 0; phe ^= 1; }
            }
            load_slice(r % STAGES, r * KCH);
        }

        mbar_wait(mb_full + 8 * stc, phc);
        const uint32_t ab = sb + OFF_A + stc * ABYTES;
        const uint32_t bb = sb + OFF_B + stc * BBYTES;
#pragma unroll
        for (int ks = 0; ks < 2; ++ks) {
            const int k0 = ks * 16;
            uint32_t a[4][4], b[8][2];
#pragma unroll
            for (int mi = 0; mi < 4; ++mi) {
                const uint32_t addr = ab + (wm * 64 + mi * 16 + (lane & 15)) * 80
                                    + (k0 + (lane >> 4) * 8) * 2;
                asm volatile(
                    "ldmatrix.sync.aligned.m8n8.x4.shared.b16 {%0,%1,%2,%3}, [%4];"
                    : "=r"(a[mi][0]), "=r"(a[mi][1]), "=r"(a[mi][2]), "=r"(a[mi][3])
                    : "r"(addr));
            }
#pragma unroll
            for (int np = 0; np < 4; ++np) {      // 2 n-octets per x4.trans
                const uint32_t addr = bb + (k0 + (lane & 15)) * 528
                                    + (wn * 64 + np * 16 + (lane >> 4) * 8) * 2;
                asm volatile(
                    "ldmatrix.sync.aligned.m8n8.x4.trans.shared.b16 {%0,%1,%2,%3}, [%4];"
                    : "=r"(b[2 * np][0]), "=r"(b[2 * np][1]),
                      "=r"(b[2 * np + 1][0]), "=r"(b[2 * np + 1][1])
                    : "r"(addr));
            }
#pragma unroll
            for (int mi = 0; mi < 4; ++mi)
#pragma unroll
                for (int ni = 0; ni < 8; ++ni) {
                    asm volatile(
                        "mma.sync.aligned.m16n8k16.row.col.f32.f16.f16.f32 "
                        "{%0,%1,%2,%3}, {%4,%5,%6,%7}, {%8,%9}, {%0,%1,%2,%3};"
                        : "+f"(acc[mi][ni][0]), "+f"(acc[mi][ni][1]),
                          "+f"(acc[mi][ni][2]), "+f"(acc[mi][ni][3])
                        : "r"(a[mi][0]), "r"(a[mi][1]), "r"(a[mi][2]), "r"(a[mi][3]),
                          "r"(b[ni][0]), "r"(b[ni][1]));
                }
        }
        if (elect_one()) mbar_arrive(mb_empty + 8 * stc);
        if (++stc == STAGES) { stc = 0; phc ^= 1; }
    }

    // Epilogue: tanh(acc + dec_f) * v, reduce over this tile's 256 N cols.
    float pr[4][2];
#pragma unroll
    for (int mi = 0; mi < 4; ++mi) { pr[mi][0] = 0.f; pr[mi][1] = 0.f; }
#pragma unroll
    for (int mi = 0; mi < 4; ++mi)
#pragma unroll
        for (int ni = 0; ni < 8; ++ni) {
            const int col = wn * 64 + ni * 8 + tq * 2;
            const float t0 = t_s[col], t1 = t_s[col + 1];
            const float v0 = v_s[col], v1 = v_s[col + 1];
            pr[mi][0] += fast_tanh(acc[mi][ni][0] + t0) * v0
                       + fast_tanh(acc[mi][ni][1] + t1) * v1;
            pr[mi][1] += fast_tanh(acc[mi][ni][2] + t0) * v0
                       + fast_tanh(acc[mi][ni][3] + t1) * v1;
        }
#pragma unroll
    for (int mi = 0; mi < 4; ++mi)
#pragma unroll
        for (int hh = 0; hh < 2; ++hh) {
            float x = pr[mi][hh];
            x += __shfl_xor_sync(0xffffffffu, x, 1);
            x += __shfl_xor_sync(0xffffffffu, x, 2);
            pr[mi][hh] = x;
        }
    float* pe = (float*)(sm + OFF_PE);           // [4 wn][128 rows]
    __syncthreads();
    if (tq == 0) {
#pragma unroll
        for (int mi = 0; mi < 4; ++mi) {
            const int row = wm * 64 + mi * 16 + g;
            pe[wn * MT + row]     = pr[mi][0];
            pe[wn * MT + row + 8] = pr[mi][1];
        }
    }
    __syncthreads();
    if (tid < MT)
        g_pe[(size_t)nt * BS + m0 + tid] =
            pe[tid] + pe[MT + tid] + pe[2 * MT + tid] + pe[3 * MT + tid];
}

// ---------------------------------------------------------------------------
// Kernel 2: sum partials, mask, softmax over S per batch row.
// ---------------------------------------------------------------------------
__global__ void softmax_kernel(const int* __restrict__ mask,
                               float* __restrict__ attn) {
    __shared__ float e_s[Ss];
    __shared__ float red[256];
    const int b = blockIdx.x, tid = threadIdx.x;
    const size_t r0 = (size_t)b * Ss;
    for (int s = tid; s < Ss; s += 256) {
        const size_t r = r0 + s;
        float e = 0.f;
#pragma unroll
        for (int c = 0; c < NTILES; ++c) e += g_pe[(size_t)c * BS + r];
        if (mask[r] == 0) e = -1e10f;
        e_s[s] = e;
    }
    __syncthreads();
    float m = -INFINITY;
    for (int s = tid; s < Ss; s += 256) m = fmaxf(m, e_s[s]);
    red[tid] = m; __syncthreads();
    for (int o = 128; o > 0; o >>= 1) {
        if (tid < o) red[tid] = fmaxf(red[tid], red[tid + o]);
        __syncthreads();
    }
    const float rowmax = red[0]; __syncthreads();
    float lsum = 0.f;
    for (int s = tid; s < Ss; s += 256) {
        const float ex = expf(e_s[s] - rowmax);
        e_s[s] = ex; lsum += ex;
    }
    red[tid] = lsum; __syncthreads();
    for (int o = 128; o > 0; o >>= 1) {
        if (tid < o) red[tid] += red[tid + o];
        __syncthreads();
    }
    const float inv = 1.0f / red[0];
    for (int s = tid; s < Ss; s += 256) attn[r0 + s] = e_s[s] * inv;
}

// ---------------------------------------------------------------------------
// Kernel 3: context[b,e] = sum_s attn[b,s] * Eh[b,s,e]  (fp16 E copy; HBM-bound)
// ---------------------------------------------------------------------------
__global__ void context_kernel(const float* __restrict__ attn,
                               float* __restrict__ ctx) {
    __shared__ float w_s[Ss];
    const int b = blockIdx.y;
    const int e = (blockIdx.x * 256 + threadIdx.x) * 2;
    for (int s = threadIdx.x; s < Ss; s += 256) w_s[s] = attn[(size_t)b * Ss + s];
    __syncthreads();
    const __half* Eb = g_Eh + (size_t)b * Ss * Kk;
    float ax = 0.f, ay = 0.f, bx = 0.f, by = 0.f;
    for (int s = 0; s < Ss; s += 2) {
        const float w0 = w_s[s], w1 = w_s[s + 1];
        float2 f0 = __half22float2(*reinterpret_cast<const __half2*>(
            &Eb[(size_t)s * Kk + e]));
        float2 f1 = __half22float2(*reinterpret_cast<const __half2*>(
            &Eb[(size_t)(s + 1) * Kk + e]));
        ax += w0 * f0.x; ay += w0 * f0.y;
        bx += w1 * f1.x; by += w1 * f1.y;
    }
    ctx[(size_t)b * Kk + e]     = ax + bx;
    ctx[(size_t)b * Kk + e + 1] = ay + by;
}

// ---------------------------------------------------------------------------
extern "C" void kernel_launch(void* const* d_in, const int* in_sizes, int n_in,
                              void* d_out, int out_size) {
    const float* dh   = (const float*)d_in[0];
    const float* E    = (const float*)d_in[1];
    const int*   mask = (const int*)d_in[2];
    const float* Wh   = (const float*)d_in[3];
    const float* Ws   = (const float*)d_in[4];
    const float* v    = (const float*)d_in[5];

    float* out  = (float*)d_out;
    float* ctx  = out;                        // [B, 2H]
    float* attn = out + (size_t)Bb * Kk;      // [B, S]

    // Idempotent, non-stream host call: safe under graph capture, no static guard.
    cudaFuncSetAttribute(energy_kernel,
                         cudaFuncAttributeMaxDynamicSharedMemorySize, SM_TOTAL);

    decf_kernel<<<dim3(Hh / 128, Bb), 128>>>(dh, Wh);
    cvt_ws_kernel<<<(Kk * Hh / 4) / 256, 256>>>(Ws);
    cvt_e_kernel<<<(int)(((size_t)BS * Kk / 4) / 256), 256>>>(E);
    energy_kernel<<<dim3(NTILES, BS / MT), 256, SM_TOTAL>>>(v);
    softmax_kernel<<<Bb, 256>>>(mask, attn);
    context_kernel<<<dim3(Kk / 512, Bb), 256>>>(attn, ctx);
}